// round 13
// baseline (speedup 1.0000x reference)
#include <cuda_runtime.h>
#include <cuda_bf16.h>
#include <math_constants.h>
#include <cstdint>

// Problem constants
#define D        512
#define KCODES   1024
#define NMAX     16384
#define MARGIN   2e-3f
#define MAXC     16          // per-row candidate list capacity

// ---------------------------------------------------------------------------
// Scratch (device globals; no cudaMalloc allowed)
// ---------------------------------------------------------------------------
__device__ float         g_eSq[KCODES];
__device__ float         g_xSq[NMAX];
__device__ double        g_acc;
__device__ __align__(16) __nv_bfloat16 g_Ebf[(size_t)KCODES * D];   // 1 MB
__device__ int           g_candCnt[NMAX];
__device__ int           g_cand[NMAX][MAXC];

// ---------------------------------------------------------------------------
// PTX wrappers (base-target instructions only: ldmatrix / mma.sync / cp.async)
// ---------------------------------------------------------------------------
__device__ __forceinline__ uint32_t smem_u32(const void* p) {
    uint32_t a;
    asm("{ .reg .u64 t; cvta.to.shared.u64 t, %1; cvt.u32.u64 %0, t; }"
        : "=r"(a) : "l"(p));
    return a;
}
__device__ __forceinline__ void ldmatrix_x4(uint32_t r[4], uint32_t addr) {
    asm volatile("ldmatrix.sync.aligned.m8n8.x4.shared.b16 {%0,%1,%2,%3}, [%4];"
                 : "=r"(r[0]), "=r"(r[1]), "=r"(r[2]), "=r"(r[3]) : "r"(addr));
}
__device__ __forceinline__ void ldmatrix_x2(uint32_t r[2], uint32_t addr) {
    asm volatile("ldmatrix.sync.aligned.m8n8.x2.shared.b16 {%0,%1}, [%2];"
                 : "=r"(r[0]), "=r"(r[1]) : "r"(addr));
}
__device__ __forceinline__ void mma_bf16(float d[4], const uint32_t a[4],
                                         const uint32_t b[2]) {
    asm volatile(
        "mma.sync.aligned.m16n8k16.row.col.f32.bf16.bf16.f32 "
        "{%0,%1,%2,%3}, {%4,%5,%6,%7}, {%8,%9}, {%0,%1,%2,%3};"
        : "+f"(d[0]), "+f"(d[1]), "+f"(d[2]), "+f"(d[3])
        : "r"(a[0]), "r"(a[1]), "r"(a[2]), "r"(a[3]), "r"(b[0]), "r"(b[1]));
}
#define CP_ASYNC16(dst, src) \
    asm volatile("cp.async.cg.shared.global [%0], [%1], 16;" \
                 :: "r"(dst), "l"(src) : "memory")
#define CP_COMMIT() asm volatile("cp.async.commit_group;" ::: "memory")
#define CP_WAIT(n)  asm volatile("cp.async.wait_group %0;" :: "n"(n) : "memory")

// Order-preserving float <-> uint key for atomicMin on scores
__device__ __forceinline__ uint32_t fkey(float f) {
    uint32_t u = __float_as_uint(f);
    return (u & 0x80000000u) ? ~u : (u | 0x80000000u);
}
__device__ __forceinline__ float fkey_dec(uint32_t k) {
    uint32_t u = (k & 0x80000000u) ? (k ^ 0x80000000u) : ~k;
    return __uint_as_float(u);
}

// ---------------------------------------------------------------------------
// Kernel 0: zero the loss accumulator
// ---------------------------------------------------------------------------
__global__ void zero_kernel() { g_acc = 0.0; }

// ---------------------------------------------------------------------------
// Kernel 1: eSq[k] = sum(E[k,:]^2)  AND  E -> bf16 (fused)
// ---------------------------------------------------------------------------
__global__ void esq_kernel(const float* __restrict__ E) {
    int c = blockIdx.x;
    const float4* row = reinterpret_cast<const float4*>(E + (size_t)c * D);
    int t = threadIdx.x;
    float4 v = row[t];
    __nv_bfloat162 p0 = __floats2bfloat162_rn(v.x, v.y);
    __nv_bfloat162 p1 = __floats2bfloat162_rn(v.z, v.w);
    *reinterpret_cast<__nv_bfloat162*>(&g_Ebf[(size_t)c * D + t * 4])     = p0;
    *reinterpret_cast<__nv_bfloat162*>(&g_Ebf[(size_t)c * D + t * 4 + 2]) = p1;

    float s = v.x * v.x + v.y * v.y + v.z * v.z + v.w * v.w;
    #pragma unroll
    for (int off = 16; off > 0; off >>= 1)
        s += __shfl_down_sync(0xFFFFFFFFu, s, off);
    __shared__ float ws[4];
    if ((t & 31) == 0) ws[t >> 5] = s;
    __syncthreads();
    if (t == 0) g_eSq[c] = ws[0] + ws[1] + ws[2] + ws[3];
}

// ---------------------------------------------------------------------------
// Kernel 1b: xSq[n] = strict sequential fp32 sum of squares (reference order)
// ---------------------------------------------------------------------------
__global__ void xsq_kernel(const float* __restrict__ X) {
    __shared__ float buf[8][512];
    int w    = threadIdx.x >> 5;
    int lane = threadIdx.x & 31;
    int row  = blockIdx.x * 8 + w;
    const float4* src = reinterpret_cast<const float4*>(X + (size_t)row * D);
    #pragma unroll
    for (int i = 0; i < 4; i++) {
        float4 v = src[lane + 32 * i];
        *reinterpret_cast<float4*>(&buf[w][(lane + 32 * i) * 4]) = v;
    }
    __syncwarp();
    if (lane == 0) {
        float s = 0.0f;
        #pragma unroll 16
        for (int i = 0; i < 512; i++) {
            float x = buf[w][i];
            s = __fadd_rn(s, __fmul_rn(x, x));
        }
        g_xSq[row] = s;
    }
}

// ---------------------------------------------------------------------------
// Kernel 2: SCREEN — bf16 mma.sync GEMM with FUSED candidate selection.
// 128 CTAs x 256 threads. A (128x512 bf16) persistent in smem; B streamed
// via 4-stage cp.async. Per code-tile epilogue: running per-row min via smem
// atomicMin (order-preserving keys), then append codes with
// score < runningMin + MARGIN to a per-row candidate list.
// Superset guarantee: runningMin >= finalMin, and 2*|bf16 dot err| < MARGIN.
// No score matrix in gmem at all.
// ---------------------------------------------------------------------------
#define A_STRIDE 520
#define B_STRIDE 72
#define NSTAGE   4
#define BSTG_HALVES (128 * B_STRIDE)
#define SM_A_BYTES   (128 * A_STRIDE * 2)                 // 133120
#define SM_B_BYTES   (NSTAGE * BSTG_HALVES * 2)           // 73728
#define SM_ESQ_OFF   (SM_A_BYTES + SM_B_BYTES)            // 206848 (4096 B)
#define SM_RMIN_OFF  (SM_ESQ_OFF + 4096)                  // 210944 (512 B)
#define SM_CNT_OFF   (SM_RMIN_OFF + 512)                  // 211456 (512 B)
#define SM_CAND_OFF  (SM_CNT_OFF + 512)                   // 211968 (8192 B)
#define SM_SCR_TOTAL (SM_CAND_OFF + 128 * MAXC * 4)       // 220160

__global__ __launch_bounds__(256, 1)
void screen_kernel(const float* __restrict__ X) {
    extern __shared__ char sm[];
    __nv_bfloat16* Asm   = reinterpret_cast<__nv_bfloat16*>(sm);
    float*         esm   = reinterpret_cast<float*>(sm + SM_ESQ_OFF);
    uint32_t*      rmin  = reinterpret_cast<uint32_t*>(sm + SM_RMIN_OFF);
    int*           ccnt  = reinterpret_cast<int*>(sm + SM_CNT_OFF);
    int*           cands = reinterpret_cast<int*>(sm + SM_CAND_OFF);  // [128][MAXC]

    const int tid  = threadIdx.x;
    const int lane = tid & 31;
    const int wid  = tid >> 5;
    const int wm   = wid >> 2;          // 0..1 (64-row group)
    const int wn   = wid & 3;           // 0..3 (32-code group)
    const int rowBase = blockIdx.x * 128;

    const uint32_t sA = smem_u32(sm);
    const uint32_t sB = sA + SM_A_BYTES;

    // cp.async issue for pipeline step s
    const int ldR  = tid >> 3;          // 0..31
    const int ldKq = (tid & 7) * 8;
    auto issue = [&](int s) {
        if (s < 64) {
            int nt = s >> 3, c = s & 7;
            const __nv_bfloat16* src =
                g_Ebf + (size_t)(nt * 128 + ldR) * D + c * 64 + ldKq;
            uint32_t dst = sB + (uint32_t)((s & (NSTAGE - 1)) * BSTG_HALVES) * 2
                              + (uint32_t)(ldR * B_STRIDE + ldKq) * 2;
            #pragma unroll
            for (int l = 0; l < 4; l++) {
                CP_ASYNC16(dst + (uint32_t)(32 * B_STRIDE * 2) * l,
                           src + (size_t)(32 * l) * D);
            }
        }
        CP_COMMIT();
    };

    issue(0); issue(1); issue(2);

    // A: X[rowBase..+128][:] -> bf16 smem; init selection state
    #pragma unroll 4
    for (int i = 0; i < 64; i++) {
        int f = tid + i * 256;
        int r = f >> 7;
        int k = (f & 127) << 2;
        float4 v = *reinterpret_cast<const float4*>(&X[(size_t)(rowBase + r) * D + k]);
        __nv_bfloat162 p0 = __floats2bfloat162_rn(v.x, v.y);
        __nv_bfloat162 p1 = __floats2bfloat162_rn(v.z, v.w);
        *reinterpret_cast<__nv_bfloat162*>(&Asm[r * A_STRIDE + k])     = p0;
        *reinterpret_cast<__nv_bfloat162*>(&Asm[r * A_STRIDE + k + 2]) = p1;
    }
    for (int i = tid; i < KCODES; i += 256) esm[i] = g_eSq[i];
    if (tid < 128) { rmin[tid] = 0xFFFFFFFFu; ccnt[tid] = 0; }
    __syncthreads();

    const int aRowLane = ((lane >> 3) & 1) * 8 + (lane & 7);
    const int aKLane   = ((lane >> 4) & 1) * 8;
    const int bRowLane = lane & 7;
    const int bKLane   = ((lane >> 3) & 1) * 8;

    float acc[4][4][4];
    #pragma unroll
    for (int mi = 0; mi < 4; mi++)
        #pragma unroll
        for (int ni = 0; ni < 4; ni++)
            #pragma unroll
            for (int q = 0; q < 4; q++) acc[mi][ni][q] = 0.0f;

    for (int s = 0; s < 64; s++) {
        const int nt = s >> 3, c = s & 7;
        CP_WAIT(NSTAGE - 2);
        __syncthreads();
        issue(s + NSTAGE - 1);

        const uint32_t bufB = sB + (uint32_t)((s & (NSTAGE - 1)) * BSTG_HALVES) * 2;
        #pragma unroll
        for (int ks = 0; ks < 4; ks++) {
            uint32_t afr[4][4];
            const int kk = c * 64 + ks * 16 + aKLane;
            #pragma unroll
            for (int mi = 0; mi < 4; mi++) {
                int r = wm * 64 + mi * 16 + aRowLane;
                ldmatrix_x4(afr[mi], sA + (uint32_t)(r * A_STRIDE + kk) * 2);
            }
            uint32_t bfr[4][2];
            const int kb = ks * 16 + bKLane;
            #pragma unroll
            for (int ni = 0; ni < 4; ni++) {
                int r = wn * 32 + ni * 8 + bRowLane;
                ldmatrix_x2(bfr[ni], bufB + (uint32_t)(r * B_STRIDE + kb) * 2);
            }
            #pragma unroll
            for (int mi = 0; mi < 4; mi++)
                #pragma unroll
                for (int ni = 0; ni < 4; ni++)
                    mma_bf16(acc[mi][ni], afr[mi], bfr[ni]);
        }

        if (c == 7) {
            // ---- fused selection epilogue for code tile nt ----
            const int nbase = nt * 128;
            // per-lane esq values for its 8 columns
            float esv[4][2];
            #pragma unroll
            for (int ni = 0; ni < 4; ni++) {
                int col = nbase + wn * 32 + ni * 8 + (lane & 3) * 2;
                esv[ni][0] = esm[col];
                esv[ni][1] = esm[col + 1];
            }
            // phase 1: per-row running min via atomicMin
            #pragma unroll
            for (int mi = 0; mi < 4; mi++) {
                #pragma unroll
                for (int h = 0; h < 2; h++) {
                    float vmin = CUDART_INF_F;
                    #pragma unroll
                    for (int ni = 0; ni < 4; ni++) {
                        float s0 = esv[ni][0] - 2.0f * acc[mi][ni][2 * h];
                        float s1 = esv[ni][1] - 2.0f * acc[mi][ni][2 * h + 1];
                        vmin = fminf(vmin, fminf(s0, s1));
                    }
                    vmin = fminf(vmin, __shfl_xor_sync(0xFFFFFFFFu, vmin, 1));
                    vmin = fminf(vmin, __shfl_xor_sync(0xFFFFFFFFu, vmin, 2));
                    if ((lane & 3) == 0) {
                        int rloc = wm * 64 + mi * 16 + (lane >> 2) + h * 8;
                        atomicMin(&rmin[rloc], fkey(vmin));
                    }
                }
            }
            __syncthreads();   // all tiles' atomicMin visible
            // phase 2: append candidates below runningMin + MARGIN
            #pragma unroll
            for (int mi = 0; mi < 4; mi++) {
                #pragma unroll
                for (int h = 0; h < 2; h++) {
                    int rloc = wm * 64 + mi * 16 + (lane >> 2) + h * 8;
                    float th = fkey_dec(rmin[rloc]) + MARGIN;
                    #pragma unroll
                    for (int ni = 0; ni < 4; ni++) {
                        int col = nbase + wn * 32 + ni * 8 + (lane & 3) * 2;
                        float s0 = esv[ni][0] - 2.0f * acc[mi][ni][2 * h];
                        float s1 = esv[ni][1] - 2.0f * acc[mi][ni][2 * h + 1];
                        if (s0 < th) {
                            int p = atomicAdd(&ccnt[rloc], 1);
                            if (p < MAXC) cands[rloc * MAXC + p] = col;
                        }
                        if (s1 < th) {
                            int p = atomicAdd(&ccnt[rloc], 1);
                            if (p < MAXC) cands[rloc * MAXC + p] = col + 1;
                        }
                        acc[mi][ni][2 * h]     = 0.0f;
                        acc[mi][ni][2 * h + 1] = 0.0f;
                    }
                }
            }
            __syncthreads();   // appends done before next tile's atomicMin
        }
    }

    // write candidate lists to gmem
    if (tid < 128) {
        int cnt = ccnt[tid];
        g_candCnt[rowBase + tid] = cnt;
        int m = cnt < MAXC ? cnt : MAXC;
        for (int i = 0; i < m; i++)
            g_cand[rowBase + tid][i] = cands[tid * MAXC + i];
    }
}

// ---------------------------------------------------------------------------
// Kernel 3: RESCUE — exact fp32 scoring of candidates + gather + loss.
// One warp per row (8 warps / 256-thread block). Exact quantized score
// fl((xsq+esq) - fl(2*dot)) with first-index tie-break == reference.
// Overflowed rows (> MAXC candidates) fall back to a full exact scan.
// ---------------------------------------------------------------------------
__global__ __launch_bounds__(256)
void rescue_kernel(const float* __restrict__ X, const float* __restrict__ E,
                   float* __restrict__ outQ, float* __restrict__ outIdx) {
    const int w    = threadIdx.x >> 5;
    const int lane = threadIdx.x & 31;
    const int row  = blockIdx.x * 8 + w;

    // X row, lane-strided (16 floats/lane, coalesced)
    float xr[16];
    #pragma unroll
    for (int t = 0; t < 16; t++) xr[t] = X[(size_t)row * D + lane + 32 * t];
    const float xs = g_xSq[row];

    float bv = CUDART_INF_F;
    int   bi = 0x7fffffff;
    int cnt = g_candCnt[row];

    if (cnt <= MAXC) {
        for (int i = 0; i < cnt; i++) {
            int code = g_cand[row][i];
            const float* e = E + (size_t)code * D;
            float p = 0.0f;
            #pragma unroll
            for (int t = 0; t < 16; t++) p = fmaf(xr[t], e[lane + 32 * t], p);
            #pragma unroll
            for (int off = 16; off > 0; off >>= 1)
                p += __shfl_xor_sync(0xFFFFFFFFu, p, off);
            float v = __fsub_rn(__fadd_rn(xs, g_eSq[code]), __fmul_rn(2.0f, p));
            if (v < bv || (v == bv && code < bi)) { bv = v; bi = code; }
        }
    } else {
        // overflow fallback: full exact scan (expected ~never)
        for (int code = 0; code < KCODES; code++) {
            const float* e = E + (size_t)code * D;
            float p = 0.0f;
            #pragma unroll
            for (int t = 0; t < 16; t++) p = fmaf(xr[t], e[lane + 32 * t], p);
            #pragma unroll
            for (int off = 16; off > 0; off >>= 1)
                p += __shfl_xor_sync(0xFFFFFFFFu, p, off);
            float v = __fsub_rn(__fadd_rn(xs, g_eSq[code]), __fmul_rn(2.0f, p));
            if (v < bv || (v == bv && code < bi)) { bv = v; bi = code; }
        }
    }
    // bi is identical on all lanes (xor-reduced p is lane-uniform)

    // gather + loss (outQ is 4B-aligned only -> scalar stores, coalesced)
    const float* e = E + (size_t)bi * D;
    float* q = outQ + (size_t)row * D;
    float s = 0.0f;
    #pragma unroll
    for (int t = 0; t < 16; t++) {
        float ev = e[lane + 32 * t];
        q[lane + 32 * t] = ev;
        float d = ev - xr[t];
        s = fmaf(d, d, s);
    }
    #pragma unroll
    for (int off = 16; off > 0; off >>= 1)
        s += __shfl_down_sync(0xFFFFFFFFu, s, off);
    if (lane == 0) {
        atomicAdd(&g_acc, (double)s);
        outIdx[row] = (float)bi;
    }
}

// ---------------------------------------------------------------------------
// Kernel 4: finalize loss = 1.25 * mean((q-x)^2)
// ---------------------------------------------------------------------------
__global__ void finalize_kernel(float* __restrict__ outLoss, int n) {
    outLoss[0] = (float)(1.25 * g_acc / ((double)n * (double)D));
}

// ---------------------------------------------------------------------------
extern "C" void kernel_launch(void* const* d_in, const int* in_sizes, int n_in,
                              void* d_out, int out_size) {
    const float* X = (const float*)d_in[0];   // [N, 512]
    const float* E = (const float*)d_in[1];   // [1024, 512]

    const int N = in_sizes[0] / D;            // 16384

    float* out      = (float*)d_out;
    float* outLoss  = out;
    float* outQ     = out + 1;
    float* outIdx   = out + 1 + (size_t)N * D;

    cudaFuncSetAttribute(screen_kernel,
                         cudaFuncAttributeMaxDynamicSharedMemorySize, SM_SCR_TOTAL);

    zero_kernel<<<1, 1>>>();
    esq_kernel<<<KCODES, 128>>>(E);
    xsq_kernel<<<N / 8, 256>>>(X);
    screen_kernel<<<N / 128, 256, SM_SCR_TOTAL>>>(X);
    rescue_kernel<<<N / 8, 256>>>(X, E, outQ, outIdx);
    finalize_kernel<<<1, 1>>>(outLoss, N);
}